// round 5
// baseline (speedup 1.0000x reference)
#include <cuda_runtime.h>

#define BATCH 128
#define DIM   65536
#define NELEM (BATCH * DIM)

// ---- scratch / precomputed tables (static device memory; no runtime allocs) ----
static __device__ float2 g_bufA[NELEM];          // 64 MB
static __device__ float2 g_bufB[NELEM];          // 64 MB
static __device__ float  g_partials[BATCH * 16];
static __device__ float2 g_cs[3][16];            // (cos(th/2), sin(th/2)) per layer/wire
static __device__ float2 g_Dhi[3][256];          // diagonal phase, wires 0..7  (bits 15..8)
static __device__ float2 g_Dlo[3][256];          // diagonal phase, wires 8..15 (bits 7..0)
static __device__ float  g_Ghi[256];             // head-weighted Z signs, wires 0..7
static __device__ float  g_Glo[256];             // head-weighted Z signs, wires 8..15

// smem swizzle: conflict-free for the stride-1/16/256 access patterns below.
// Bijective: bits0..3 ^= bits4..7, bit4 ^= bit8.
__device__ __forceinline__ int swz(int i) {
    return i ^ ((i >> 4) & 15) ^ (((i >> 8) & 1) << 4);
}

// Composite CNOT-ring permutation (forward basis map): out[M(a)] = psi[a].
// T = suffix-XOR over 16 bits (bit p of T = XOR of bits >= p); M = T with bit15 ^= T0.
__device__ __forceinline__ int permM(int a) {
    int t = a;
    t ^= t >> 8; t ^= t >> 4; t ^= t >> 2; t ^= t >> 1;
    return t ^ ((t & 1) << 15);
}

// 4 RY butterflies on a 16-register block; local bit q of j <-> wire (wtop - q).
__device__ __forceinline__ void bfly4_real(float v[16], int layer, int wtop) {
#pragma unroll
    for (int q = 0; q < 4; q++) {
        float2 cs = g_cs[layer][wtop - q];
        float c = cs.x, s = cs.y;
#pragma unroll
        for (int j = 0; j < 16; j++) {
            if (!(j & (1 << q))) {
                int j1 = j | (1 << q);
                float x0 = v[j], x1 = v[j1];
                v[j]  = c * x0 - s * x1;
                v[j1] = s * x0 + c * x1;
            }
        }
    }
}

__device__ __forceinline__ void bfly4_cplx(float2 v[16], int layer, int wtop) {
#pragma unroll
    for (int q = 0; q < 4; q++) {
        float2 cs = g_cs[layer][wtop - q];
        float c = cs.x, s = cs.y;
#pragma unroll
        for (int j = 0; j < 16; j++) {
            if (!(j & (1 << q))) {
                int j1 = j | (1 << q);
                float2 x0 = v[j], x1 = v[j1];
                v[j]  = make_float2(c * x0.x - s * x1.x, c * x0.y - s * x1.y);
                v[j1] = make_float2(s * x0.x + c * x1.x, s * x0.y + c * x1.y);
            }
        }
    }
}

// ---- precompute gate coefficients, diagonal-phase tables, head-sign tables ----
__global__ void k_pre(const float* __restrict__ params, const float* __restrict__ head_w) {
    int t = threadIdx.x;  // 256 threads; t doubles as byte value
    if (t < 48) {
        int d = t >> 4, w = t & 15;
        float th = params[(d * 16 + w) * 2 + 0] * 0.5f;
        g_cs[d][w] = make_float2(cosf(th), sinf(th));
    }
    for (int d = 0; d < 3; d++) {
        float ah = 0.f, al = 0.f;
        for (int w = 0; w < 8; w++) {
            float ph = params[(d * 16 + w) * 2 + 1] * 0.5f;
            ah += ((t >> (7 - w)) & 1) ? -ph : ph;          // wire w <-> bit (7-w) of hi byte
        }
        for (int w = 8; w < 16; w++) {
            float ph = params[(d * 16 + w) * 2 + 1] * 0.5f;
            al += ((t >> (15 - w)) & 1) ? -ph : ph;         // wire w <-> bit (15-w) of lo byte
        }
        g_Dhi[d][t] = make_float2(cosf(ah), -sinf(ah));     // exp(-i*ah)
        g_Dlo[d][t] = make_float2(cosf(al), -sinf(al));
    }
    float gh = 0.f, gl = 0.f;
    for (int w = 0; w < 8; w++)  gh += ((t >> (7 - w)) & 1)  ? -head_w[w] : head_w[w];
    for (int w = 8; w < 16; w++) gl += ((t >> (15 - w)) & 1) ? -head_w[w] : head_w[w];
    g_Ghi[t] = gh;
    g_Glo[t] = gl;
}

// ---- pass A (layer 0, real): RY on wires 4..15 (bits 11..0), contiguous 4096 tile ----
__global__ void k_low_real(const float* __restrict__ in) {
    __shared__ float tile[4096];
    float* out = (float*)(void*)g_bufA;  // layer-0 state stays real until the diagonal
    int base = blockIdx.x << 12;
    int t = threadIdx.x;
#pragma unroll
    for (int k = 0; k < 16; k++) { int i = t + (k << 8); tile[swz(i)] = in[base + i]; }
    __syncthreads();
    {   // bits 8..11 -> wires 7..4
        float v[16];
#pragma unroll
        for (int j = 0; j < 16; j++) v[j] = tile[swz(t | (j << 8))];
        bfly4_real(v, 0, 7);
#pragma unroll
        for (int j = 0; j < 16; j++) tile[swz(t | (j << 8))] = v[j];
    }
    __syncthreads();
    {   // bits 4..7 -> wires 11..8
        int b = (t & 15) | ((t >> 4) << 8);
        float v[16];
#pragma unroll
        for (int j = 0; j < 16; j++) v[j] = tile[swz(b | (j << 4))];
        bfly4_real(v, 0, 11);
#pragma unroll
        for (int j = 0; j < 16; j++) tile[swz(b | (j << 4))] = v[j];
    }
    __syncthreads();
    {   // bits 0..3 -> wires 15..12
        int b = t << 4;
        float v[16];
#pragma unroll
        for (int j = 0; j < 16; j++) v[j] = tile[swz(b | j)];
        bfly4_real(v, 0, 15);
#pragma unroll
        for (int j = 0; j < 16; j++) tile[swz(b | j)] = v[j];
    }
    __syncthreads();
#pragma unroll
    for (int k = 0; k < 16; k++) { int i = t + (k << 8); out[base + i] = tile[swz(i)]; }
}

// ---- pass A (layers 1,2, complex, in-place) ----
__global__ void k_low_c(int layer, int whichB) {
    __shared__ float2 tile[4096];
    float2* buf = whichB ? g_bufB : g_bufA;
    int base = blockIdx.x << 12;
    int t = threadIdx.x;
#pragma unroll
    for (int k = 0; k < 16; k++) { int i = t + (k << 8); tile[swz(i)] = buf[base + i]; }
    __syncthreads();
    {
        float2 v[16];
#pragma unroll
        for (int j = 0; j < 16; j++) v[j] = tile[swz(t | (j << 8))];
        bfly4_cplx(v, layer, 7);
#pragma unroll
        for (int j = 0; j < 16; j++) tile[swz(t | (j << 8))] = v[j];
    }
    __syncthreads();
    {
        int b = (t & 15) | ((t >> 4) << 8);
        float2 v[16];
#pragma unroll
        for (int j = 0; j < 16; j++) v[j] = tile[swz(b | (j << 4))];
        bfly4_cplx(v, layer, 11);
#pragma unroll
        for (int j = 0; j < 16; j++) tile[swz(b | (j << 4))] = v[j];
    }
    __syncthreads();
    {
        int b = t << 4;
        float2 v[16];
#pragma unroll
        for (int j = 0; j < 16; j++) v[j] = tile[swz(b | j)];
        bfly4_cplx(v, layer, 15);
#pragma unroll
        for (int j = 0; j < 16; j++) tile[swz(b | j)] = v[j];
    }
    __syncthreads();
#pragma unroll
    for (int k = 0; k < 16; k++) { int i = t + (k << 8); buf[base + i] = tile[swz(i)]; }
}

// Per-block destination rows for the permutation scatter (s, mid fixed):
// dest = permM(a), a = (h<<12)|(mid<<8)|lo. Within the block, destinations form
// 16 DENSE 2KB rows: key k = dest[15:12], slot = dest[7:0], and dest[11:8] =
// sfx(mid) ^ (k0 ? 0xF : 0), with sfx = 4-bit suffix-XOR of mid. Stage rows in
// smem, then write each row fully coalesced.
__device__ __forceinline__ int sfx4(int m) { m ^= m >> 2; m ^= m >> 1; return m & 15; }

// ---- pass B (layer 0): RY wires 0..3 (bits 15..12) on real state, diagonal D0
//      (real -> complex), CNOT-ring permutation scatter (staged). bufA -> bufB. ----
__global__ void k_hi_first() {
    __shared__ float2 st[4096];
    const float* in = (const float*)(const void*)g_bufA;
    float2* out = g_bufB;
    int s = blockIdx.x >> 4, mid = blockIdx.x & 15;
    int lo = threadIdx.x;
    int sbase = s << 16;
    int abase = (mid << 8) | lo;
    float v[16];
#pragma unroll
    for (int h = 0; h < 16; h++) v[h] = in[sbase | (h << 12) | abase];
    bfly4_real(v, 0, 3);  // h bit q -> global bit 12+q -> wire 3-q
    float2 dlo = g_Dlo[0][lo];
#pragma unroll
    for (int h = 0; h < 16; h++) {
        int a = (h << 12) | abase;
        int dest = permM(a);
        float2 dh = g_Dhi[0][(a >> 8) & 255];
        float dcr = dh.x * dlo.x - dh.y * dlo.y;
        float dci = dh.x * dlo.y + dh.y * dlo.x;
        st[((dest >> 12) << 8) | (dest & 255)] = make_float2(v[h] * dcr, v[h] * dci);
    }
    __syncthreads();
    int ms = sfx4(mid);
#pragma unroll
    for (int k = 0; k < 16; k++) {
        int H = (k << 4) | (ms ^ ((k & 1) ? 15 : 0));     // dest bits 8..15
        out[sbase | (H << 8) | lo] = st[(k << 8) | lo];
    }
}

// ---- pass B (layer 1): complex RY wires 0..3, diagonal, staged permutation scatter ----
__global__ void k_hi_mid(int layer, int srcIsB) {
    __shared__ float2 st[4096];
    const float2* in = srcIsB ? g_bufB : g_bufA;
    float2* out = srcIsB ? g_bufA : g_bufB;
    int s = blockIdx.x >> 4, mid = blockIdx.x & 15;
    int lo = threadIdx.x;
    int sbase = s << 16;
    int abase = (mid << 8) | lo;
    float2 v[16];
#pragma unroll
    for (int h = 0; h < 16; h++) v[h] = in[sbase | (h << 12) | abase];
    bfly4_cplx(v, layer, 3);
    float2 dlo = g_Dlo[layer][lo];
#pragma unroll
    for (int h = 0; h < 16; h++) {
        int a = (h << 12) | abase;
        int dest = permM(a);
        float2 dh = g_Dhi[layer][(a >> 8) & 255];
        float dcr = dh.x * dlo.x - dh.y * dlo.y;
        float dci = dh.x * dlo.y + dh.y * dlo.x;
        float2 x = v[h];
        st[((dest >> 12) << 8) | (dest & 255)] =
            make_float2(x.x * dcr - x.y * dci, x.x * dci + x.y * dcr);
    }
    __syncthreads();
    int ms = sfx4(mid);
#pragma unroll
    for (int k = 0; k < 16; k++) {
        int H = (k << 4) | (ms ^ ((k & 1) ? 15 : 0));
        out[sbase | (H << 8) | lo] = st[(k << 8) | lo];
    }
}

// ---- pass B (layer 2): RY wires 0..3; D2 skipped (pure phase, |.|^2 invariant);
//      final CNOT ring + PauliZ expvals + linear head folded into weighted reduce. ----
__global__ void k_hi_last() {
    const float2* in = g_bufA;
    int s = blockIdx.x >> 4, mid = blockIdx.x & 15;
    int lo = threadIdx.x;
    int sbase = s << 16;
    int abase = (mid << 8) | lo;
    float2 v[16];
#pragma unroll
    for (int h = 0; h < 16; h++) v[h] = in[sbase | (h << 12) | abase];
    bfly4_cplx(v, 2, 3);
    float acc = 0.f;
#pragma unroll
    for (int h = 0; h < 16; h++) {
        int y = permM((h << 12) | abase);
        float g = g_Ghi[(y >> 8) & 255] + g_Glo[y & 255];
        acc += (v[h].x * v[h].x + v[h].y * v[h].y) * g;
    }
#pragma unroll
    for (int o = 16; o; o >>= 1) acc += __shfl_xor_sync(0xFFFFFFFFu, acc, o);
    __shared__ float red[8];
    if ((threadIdx.x & 31) == 0) red[threadIdx.x >> 5] = acc;
    __syncthreads();
    if (threadIdx.x == 0) {
        float tt = 0.f;
#pragma unroll
        for (int i = 0; i < 8; i++) tt += red[i];
        g_partials[blockIdx.x] = tt;
    }
}

__global__ void k_final(const float* __restrict__ head_b, float* __restrict__ out) {
    int s = threadIdx.x;  // 128
    float a = 0.f;
#pragma unroll
    for (int m = 0; m < 16; m++) a += g_partials[(s << 4) + m];
    out[s] = head_b[0] + a;
}

extern "C" void kernel_launch(void* const* d_in, const int* in_sizes, int n_in,
                              void* d_out, int out_size) {
    const float* state  = (const float*)d_in[0];  // (128, 65536)
    const float* params = (const float*)d_in[1];  // (3, 16, 2)
    const float* head_w = (const float*)d_in[2];  // (1, 16)
    const float* head_b = (const float*)d_in[3];  // (1,)
    float* out = (float*)d_out;                   // (128,)
    (void)in_sizes; (void)n_in; (void)out_size;

    k_pre<<<1, 256>>>(params, head_w);

    // Layer 0: real RY low wires -> real RY high wires + D0 + perm (-> bufB)
    k_low_real<<<2048, 256>>>(state);
    k_hi_first<<<2048, 256>>>();

    // Layer 1: complex, in-place low pass on bufB, then D1 + perm bufB -> bufA
    k_low_c<<<2048, 256>>>(1, 1);
    k_hi_mid<<<2048, 256>>>(1, 1);

    // Layer 2: complex, in-place low pass on bufA, then fused measure/head
    k_low_c<<<2048, 256>>>(2, 0);
    k_hi_last<<<2048, 256>>>();

    k_final<<<1, 128>>>(head_b, out);
}

// round 6
// speedup vs baseline: 1.5684x; 1.5684x over previous
#include <cuda_runtime.h>

#define BATCH 128
#define DIM   65536
#define NELEM (BATCH * DIM)

typedef unsigned long long u64;

// ---- scratch / precomputed tables (static device memory; no runtime allocs) ----
static __device__ float2 g_bufA[NELEM];          // 64 MB
static __device__ float2 g_bufB[NELEM];          // 64 MB
static __device__ float  g_partials[BATCH * 16];
static __device__ float2 g_cs[3][16];            // (cos(th/2), sin(th/2)) per layer/wire
static __device__ float2 g_Dhi[3][256];          // diagonal phase, wires 0..7  (bits 15..8)
static __device__ float2 g_Dlo[3][256];          // diagonal phase, wires 8..15 (bits 7..0)
static __device__ float  g_Ghi[256];             // head-weighted Z signs, wires 0..7
static __device__ float  g_Glo[256];             // head-weighted Z signs, wires 8..15

// ---- packed f32x2 helpers (FFMA2 path: PTX-only, ptxas won't fuse from C++) ----
__device__ __forceinline__ u64 pk(float x, float y) {
    u64 r; asm("mov.b64 %0,{%1,%2};" : "=l"(r) : "f"(x), "f"(y)); return r;
}
__device__ __forceinline__ void upk(u64 a, float& x, float& y) {
    asm("mov.b64 {%0,%1},%2;" : "=f"(x), "=f"(y) : "l"(a));
}
__device__ __forceinline__ u64 fma2(u64 a, u64 b, u64 c) {
    u64 r; asm("fma.rn.f32x2 %0,%1,%2,%3;" : "=l"(r) : "l"(a), "l"(b), "l"(c)); return r;
}
__device__ __forceinline__ u64 mul2(u64 a, u64 b) {
    u64 r; asm("mul.rn.f32x2 %0,%1,%2;" : "=l"(r) : "l"(a), "l"(b)); return r;
}

// smem swizzle: conflict-free for the stride-1/16/256 access patterns below.
// Bijective: bits0..3 ^= bits4..7, bit4 ^= bit8.
__device__ __forceinline__ int swz(int i) {
    return i ^ ((i >> 4) & 15) ^ (((i >> 8) & 1) << 4);
}

// Composite CNOT-ring permutation (forward basis map): out[M(a)] = psi[a].
// T = suffix-XOR over 16 bits; M = T with bit15 ^= T0 (global parity).
__device__ __forceinline__ int permM(int a) {
    int t = a;
    t ^= t >> 8; t ^= t >> 4; t ^= t >> 2; t ^= t >> 1;
    return t ^ ((t & 1) << 15);
}

// 4 RY butterflies on a 16-register block; local bit q of j <-> wire (wtop - q).
__device__ __forceinline__ void bfly4_real(float v[16], int layer, int wtop) {
#pragma unroll
    for (int q = 0; q < 4; q++) {
        float2 cs = g_cs[layer][wtop - q];
        float c = cs.x, s = cs.y;
#pragma unroll
        for (int j = 0; j < 16; j++) {
            if (!(j & (1 << q))) {
                int j1 = j | (1 << q);
                float x0 = v[j], x1 = v[j1];
                v[j]  = c * x0 - s * x1;
                v[j1] = s * x0 + c * x1;
            }
        }
    }
}

// Packed complex version: each u64 holds (re, im); RY coeffs broadcast to both halves.
__device__ __forceinline__ void bfly4_pk(u64 v[16], int layer, int wtop) {
#pragma unroll
    for (int q = 0; q < 4; q++) {
        float2 cs = g_cs[layer][wtop - q];
        u64 cc = pk(cs.x, cs.x), sp = pk(cs.y, cs.y), sn = pk(-cs.y, -cs.y);
#pragma unroll
        for (int j = 0; j < 16; j++) {
            if (!(j & (1 << q))) {
                int j1 = j | (1 << q);
                u64 x0 = v[j], x1 = v[j1];
                v[j]  = fma2(sn, x1, mul2(cc, x0));   // c*x0 - s*x1 (both comps)
                v[j1] = fma2(sp, x0, mul2(cc, x1));   // s*x0 + c*x1
            }
        }
    }
}

// ---- precompute gate coefficients, diagonal-phase tables, head-sign tables ----
__global__ void k_pre(const float* __restrict__ params, const float* __restrict__ head_w) {
    int t = threadIdx.x;  // 256 threads; t doubles as byte value
    if (t < 48) {
        int d = t >> 4, w = t & 15;
        float th = params[(d * 16 + w) * 2 + 0] * 0.5f;
        g_cs[d][w] = make_float2(cosf(th), sinf(th));
    }
    for (int d = 0; d < 3; d++) {
        float ah = 0.f, al = 0.f;
        for (int w = 0; w < 8; w++) {
            float ph = params[(d * 16 + w) * 2 + 1] * 0.5f;
            ah += ((t >> (7 - w)) & 1) ? -ph : ph;
        }
        for (int w = 8; w < 16; w++) {
            float ph = params[(d * 16 + w) * 2 + 1] * 0.5f;
            al += ((t >> (15 - w)) & 1) ? -ph : ph;
        }
        g_Dhi[d][t] = make_float2(cosf(ah), -sinf(ah));     // exp(-i*ah)
        g_Dlo[d][t] = make_float2(cosf(al), -sinf(al));
    }
    float gh = 0.f, gl = 0.f;
    for (int w = 0; w < 8; w++)  gh += ((t >> (7 - w)) & 1)  ? -head_w[w] : head_w[w];
    for (int w = 8; w < 16; w++) gl += ((t >> (15 - w)) & 1) ? -head_w[w] : head_w[w];
    g_Ghi[t] = gh;
    g_Glo[t] = gl;
}

// ---- pass A (layer 0, real): RY wires 4..15 (bits 11..0).
//      gmem->regs (stage1) -> smem -> regs (stage2) -> smem -> regs (stage3) -> gmem. ----
__global__ void __launch_bounds__(256) k_low_real(const float* __restrict__ in) {
    __shared__ float tile[4096];
    float* out = (float*)(void*)g_bufA;  // layer-0 state stays real until the diagonal
    int base = blockIdx.x << 12;
    int t = threadIdx.x;
    float v[16];
    // stage 1: bits 8..11 -> wires 7..4 (direct coalesced gmem loads)
#pragma unroll
    for (int j = 0; j < 16; j++) v[j] = in[base + t + (j << 8)];
    bfly4_real(v, 0, 7);
#pragma unroll
    for (int j = 0; j < 16; j++) tile[swz(t | (j << 8))] = v[j];
    __syncthreads();
    // stage 2: bits 4..7 -> wires 11..8
    {
        int b = (t & 15) | ((t >> 4) << 8);
#pragma unroll
        for (int j = 0; j < 16; j++) v[j] = tile[swz(b | (j << 4))];
        bfly4_real(v, 0, 11);
#pragma unroll
        for (int j = 0; j < 16; j++) tile[swz(b | (j << 4))] = v[j];
    }
    __syncthreads();
    // stage 3: bits 0..3 -> wires 15..12 (direct vectorized gmem stores)
    {
        int b = t << 4;
#pragma unroll
        for (int j = 0; j < 16; j++) v[j] = tile[swz(b | j)];
        bfly4_real(v, 0, 15);
        float4* o = (float4*)(out + base + b);
#pragma unroll
        for (int m = 0; m < 4; m++)
            o[m] = make_float4(v[4 * m], v[4 * m + 1], v[4 * m + 2], v[4 * m + 3]);
    }
}

// ---- pass A (layers 1,2, complex, in-place), packed f32x2, 2 smem round trips ----
__global__ void __launch_bounds__(256) k_low_c(int layer, int whichB) {
    __shared__ u64 tile[4096];
    u64* buf = (u64*)(void*)(whichB ? g_bufB : g_bufA);
    int base = blockIdx.x << 12;
    int t = threadIdx.x;
    u64 v[16];
    // stage 1: bits 8..11 (direct coalesced gmem loads, 16-deep MLP)
#pragma unroll
    for (int j = 0; j < 16; j++) v[j] = buf[base + t + (j << 8)];
    bfly4_pk(v, layer, 7);
#pragma unroll
    for (int j = 0; j < 16; j++) tile[swz(t | (j << 8))] = v[j];
    __syncthreads();
    // stage 2: bits 4..7
    {
        int b = (t & 15) | ((t >> 4) << 8);
#pragma unroll
        for (int j = 0; j < 16; j++) v[j] = tile[swz(b | (j << 4))];
        bfly4_pk(v, layer, 11);
#pragma unroll
        for (int j = 0; j < 16; j++) tile[swz(b | (j << 4))] = v[j];
    }
    __syncthreads();
    // stage 3: bits 0..3 (direct 16B-vectorized gmem stores)
    {
        int b = t << 4;
#pragma unroll
        for (int j = 0; j < 16; j++) v[j] = tile[swz(b | j)];
        bfly4_pk(v, layer, 15);
        ulonglong2* o = (ulonglong2*)(buf + base + b);
#pragma unroll
        for (int m = 0; m < 8; m++) {
            ulonglong2 w; w.x = v[2 * m]; w.y = v[2 * m + 1];
            o[m] = w;
        }
    }
}

// Per-block destination rows for the permutation scatter (s, mid fixed):
// dest = permM(a), a = (h<<12)|(mid<<8)|lo. Destinations form 16 DENSE 2KB rows:
// key k = dest[15:12], slot = dest[7:0], dest[11:8] = sfx(mid) ^ (k0 ? 0xF : 0).
__device__ __forceinline__ int sfx4(int m) { m ^= m >> 2; m ^= m >> 1; return m & 15; }

// ---- pass B (layer 0): RY wires 0..3 on real state, D0 (real->complex),
//      staged CNOT-ring permutation scatter. bufA(real) -> bufB. ----
__global__ void __launch_bounds__(256) k_hi_first() {
    __shared__ u64 st[4096];
    const float* in = (const float*)(const void*)g_bufA;
    u64* out = (u64*)(void*)g_bufB;
    int s = blockIdx.x >> 4, mid = blockIdx.x & 15;
    int lo = threadIdx.x;
    int sbase = s << 16;
    int abase = (mid << 8) | lo;
    float v[16];
#pragma unroll
    for (int h = 0; h < 16; h++) v[h] = in[sbase | (h << 12) | abase];
    bfly4_real(v, 0, 3);  // h bit q -> global bit 12+q -> wire 3-q
    float2 dlo = g_Dlo[0][lo];
#pragma unroll
    for (int h = 0; h < 16; h++) {
        int a = (h << 12) | abase;
        int dest = permM(a);
        float2 dh = g_Dhi[0][(a >> 8) & 255];
        float dcr = dh.x * dlo.x - dh.y * dlo.y;
        float dci = dh.x * dlo.y + dh.y * dlo.x;
        st[((dest >> 12) << 8) | (dest & 255)] = mul2(pk(v[h], v[h]), pk(dcr, dci));
    }
    __syncthreads();
    int ms = sfx4(mid);
#pragma unroll
    for (int k = 0; k < 16; k++) {
        int H = (k << 4) | (ms ^ ((k & 1) ? 15 : 0));     // dest bits 8..15
        out[sbase | (H << 8) | lo] = st[(k << 8) | lo];
    }
}

// ---- pass B (layer 1): packed complex RY wires 0..3, diagonal, staged scatter ----
__global__ void __launch_bounds__(256) k_hi_mid(int layer, int srcIsB) {
    __shared__ u64 st[4096];
    const u64* in = (const u64*)(const void*)(srcIsB ? g_bufB : g_bufA);
    u64* out = (u64*)(void*)(srcIsB ? g_bufA : g_bufB);
    int s = blockIdx.x >> 4, mid = blockIdx.x & 15;
    int lo = threadIdx.x;
    int sbase = s << 16;
    int abase = (mid << 8) | lo;
    u64 v[16];
#pragma unroll
    for (int h = 0; h < 16; h++) v[h] = in[sbase | (h << 12) | abase];
    bfly4_pk(v, layer, 3);
    float2 dlo = g_Dlo[layer][lo];
#pragma unroll
    for (int h = 0; h < 16; h++) {
        int a = (h << 12) | abase;
        int dest = permM(a);
        float2 dh = g_Dhi[layer][(a >> 8) & 255];
        float dcr = dh.x * dlo.x - dh.y * dlo.y;
        float dci = dh.x * dlo.y + dh.y * dlo.x;
        float xr, xi; upk(v[h], xr, xi);
        // x * (dcr + i*dci) = xr*(dcr,dci) + xi*(-dci,dcr), packed
        u64 res = fma2(pk(xi, xi), pk(-dci, dcr), mul2(pk(xr, xr), pk(dcr, dci)));
        st[((dest >> 12) << 8) | (dest & 255)] = res;
    }
    __syncthreads();
    int ms = sfx4(mid);
#pragma unroll
    for (int k = 0; k < 16; k++) {
        int H = (k << 4) | (ms ^ ((k & 1) ? 15 : 0));
        out[sbase | (H << 8) | lo] = st[(k << 8) | lo];
    }
}

// ---- pass B (layer 2): RY wires 0..3; D2 skipped (pure phase, |.|^2 invariant);
//      final CNOT ring + PauliZ expvals + linear head folded into weighted reduce. ----
__global__ void __launch_bounds__(256) k_hi_last() {
    const u64* in = (const u64*)(const void*)g_bufA;
    int s = blockIdx.x >> 4, mid = blockIdx.x & 15;
    int lo = threadIdx.x;
    int sbase = s << 16;
    int abase = (mid << 8) | lo;
    u64 v[16];
#pragma unroll
    for (int h = 0; h < 16; h++) v[h] = in[sbase | (h << 12) | abase];
    bfly4_pk(v, 2, 3);
    u64 accP = pk(0.f, 0.f);
#pragma unroll
    for (int h = 0; h < 16; h++) {
        int y = permM((h << 12) | abase);
        float g = g_Ghi[(y >> 8) & 255] + g_Glo[y & 255];
        accP = fma2(v[h], mul2(v[h], pk(g, g)), accP);   // += g*(re^2, im^2)
    }
    float ar, ai; upk(accP, ar, ai);
    float acc = ar + ai;
#pragma unroll
    for (int o = 16; o; o >>= 1) acc += __shfl_xor_sync(0xFFFFFFFFu, acc, o);
    __shared__ float red[8];
    if ((threadIdx.x & 31) == 0) red[threadIdx.x >> 5] = acc;
    __syncthreads();
    if (threadIdx.x == 0) {
        float tt = 0.f;
#pragma unroll
        for (int i = 0; i < 8; i++) tt += red[i];
        g_partials[blockIdx.x] = tt;
    }
}

__global__ void k_final(const float* __restrict__ head_b, float* __restrict__ out) {
    int s = threadIdx.x;  // 128
    float a = 0.f;
#pragma unroll
    for (int m = 0; m < 16; m++) a += g_partials[(s << 4) + m];
    out[s] = head_b[0] + a;
}

extern "C" void kernel_launch(void* const* d_in, const int* in_sizes, int n_in,
                              void* d_out, int out_size) {
    const float* state  = (const float*)d_in[0];  // (128, 65536)
    const float* params = (const float*)d_in[1];  // (3, 16, 2)
    const float* head_w = (const float*)d_in[2];  // (1, 16)
    const float* head_b = (const float*)d_in[3];  // (1,)
    float* out = (float*)d_out;                   // (128,)
    (void)in_sizes; (void)n_in; (void)out_size;

    k_pre<<<1, 256>>>(params, head_w);

    // Layer 0: real RY low wires -> real RY high wires + D0 + perm (-> bufB)
    k_low_real<<<2048, 256>>>(state);
    k_hi_first<<<2048, 256>>>();

    // Layer 1: complex, in-place low pass on bufB, then D1 + perm bufB -> bufA
    k_low_c<<<2048, 256>>>(1, 1);
    k_hi_mid<<<2048, 256>>>(1, 1);

    // Layer 2: complex, in-place low pass on bufA, then fused measure/head
    k_low_c<<<2048, 256>>>(2, 0);
    k_hi_last<<<2048, 256>>>();

    k_final<<<1, 128>>>(head_b, out);
}